// round 9
// baseline (speedup 1.0000x reference)
#include <cuda_runtime.h>
#include <math.h>
#include <stdint.h>

#define MEM_DIM 2000
#define FEA     256
#define NPIX    32768
#define HW      1024
#define SHRINK  0.0025f
#define CAP     64
#define P       8          // pixels per epilogue CTA

// 262 MB scratch for z = q @ M^T, stored transposed: z[j][n]
__device__ float g_z[(size_t)MEM_DIM * NPIX];

__device__ __forceinline__ float to_tf32(float a) {
    uint32_t r;
    asm("cvt.rna.tf32.f32 %0, %1;" : "=r"(r) : "f"(a));
    return __uint_as_float(r);
}

__device__ __forceinline__ void mma8(float* c, const uint32_t* a, const uint32_t* b) {
    asm volatile("mma.sync.aligned.m16n8k8.row.col.f32.tf32.tf32.f32 "
        "{%0,%1,%2,%3}, {%4,%5,%6,%7}, {%8,%9}, {%0,%1,%2,%3};"
        : "+f"(c[0]), "+f"(c[1]), "+f"(c[2]), "+f"(c[3])
        : "r"(a[0]), "r"(a[1]), "r"(a[2]), "r"(a[3]), "r"(b[0]), "r"(b[1]));
}

// ---------------------------------------------------------------------------
// GEMM1: z[j][n] = q[n][:]·M[j][:], tf32 3-pass split on mma.sync m16n8k8.
// CTA tile 128 pixels x 128 j, K=256 in 8 chunks of 32.
// ---------------------------------------------------------------------------
#define ASTR 136
#define GEMM_SMEM ((4 * 32 * ASTR + 128 * 33) * 4)

__global__ void __launch_bounds__(256, 2)
gemm1_tc(const float* __restrict__ x, const float* __restrict__ Mm)
{
    extern __shared__ float sm[];
    float* Ah  = sm;
    float* Al  = Ah + 32 * ASTR;
    float* Bh  = Al + 32 * ASTR;
    float* Bl  = Bh + 32 * ASTR;
    float* stg = Bl + 32 * ASTR;     // [128][33]

    const int tid  = threadIdx.x;
    const int wid  = tid >> 5;
    const int lane = tid & 31;
    const int lr   = lane >> 2;      // 0..7
    const int lc   = lane & 3;       // 0..3

    const int n0  = blockIdx.x * 128;
    const int j0  = blockIdx.y * 128;
    const int b   = n0 >> 10;
    const int hw0 = n0 & 1023;
    const float* xb = x + (size_t)b * FEA * HW + hw0;

    const int wm = (wid & 1) * 64;   // warp m (pixel) offset
    const int wn = (wid >> 1) * 32;  // warp n (j) offset

    float cacc[4][4][4];
#pragma unroll
    for (int mf = 0; mf < 4; mf++)
#pragma unroll
        for (int nf = 0; nf < 4; nf++)
#pragma unroll
            for (int r = 0; r < 4; r++) cacc[mf][nf][r] = 0.f;

    for (int c8 = 0; c8 < 8; c8++) {
        const int k0 = c8 * 32;
        __syncthreads();   // previous chunk's compute done

        // A: x is k-major -> direct conflict-free STS into [k][p]
#pragma unroll
        for (int it = 0; it < 16; it++) {
            int idx = tid + it * 256;
            int kk = idx >> 7, p = idx & 127;
            float v  = xb[(size_t)(k0 + kk) * HW + p];
            float hi = to_tf32(v);
            Ah[kk * ASTR + p] = hi;
            Al[kk * ASTR + p] = to_tf32(v - hi);
        }
        // B staging: M[j][k] coalesced -> stg[j][33]
#pragma unroll
        for (int it = 0; it < 16; it++) {
            int idx = tid + it * 256;
            int r = idx >> 5, cc = idx & 31;
            int j = j0 + r; if (j >= MEM_DIM) j = MEM_DIM - 1;
            stg[r * 33 + cc] = Mm[(size_t)j * FEA + k0 + cc];
        }
        __syncthreads();
        // transpose+split: stg[j][k] -> Bh/Bl[k][j]
#pragma unroll
        for (int it = 0; it < 16; it++) {
            int idx = tid + it * 256;
            int kk = idx >> 7, jj = idx & 127;
            float v  = stg[jj * 33 + kk];
            float hi = to_tf32(v);
            Bh[kk * ASTR + jj] = hi;
            Bl[kk * ASTR + jj] = to_tf32(v - hi);
        }
        __syncthreads();

        // ---- pass A: hh + lh (share Bh fragments) ----
#pragma unroll
        for (int ks = 0; ks < 4; ks++) {
            const int ka = ks * 8 + lc;
            uint32_t ahf[4][4], alf[4][4], bf[4][2];
#pragma unroll
            for (int mf = 0; mf < 4; mf++) {
                int p = wm + mf * 16 + lr;
                ahf[mf][0] = __float_as_uint(Ah[ka * ASTR + p]);
                ahf[mf][1] = __float_as_uint(Ah[ka * ASTR + p + 8]);
                ahf[mf][2] = __float_as_uint(Ah[(ka + 4) * ASTR + p]);
                ahf[mf][3] = __float_as_uint(Ah[(ka + 4) * ASTR + p + 8]);
                alf[mf][0] = __float_as_uint(Al[ka * ASTR + p]);
                alf[mf][1] = __float_as_uint(Al[ka * ASTR + p + 8]);
                alf[mf][2] = __float_as_uint(Al[(ka + 4) * ASTR + p]);
                alf[mf][3] = __float_as_uint(Al[(ka + 4) * ASTR + p + 8]);
            }
#pragma unroll
            for (int nf = 0; nf < 4; nf++) {
                int j = wn + nf * 8 + lr;
                bf[nf][0] = __float_as_uint(Bh[ka * ASTR + j]);
                bf[nf][1] = __float_as_uint(Bh[(ka + 4) * ASTR + j]);
            }
#pragma unroll
            for (int mf = 0; mf < 4; mf++)
#pragma unroll
                for (int nf = 0; nf < 4; nf++) mma8(cacc[mf][nf], ahf[mf], bf[nf]);
#pragma unroll
            for (int mf = 0; mf < 4; mf++)
#pragma unroll
                for (int nf = 0; nf < 4; nf++) mma8(cacc[mf][nf], alf[mf], bf[nf]);
        }
        // ---- pass B: hl ----
#pragma unroll
        for (int ks = 0; ks < 4; ks++) {
            const int ka = ks * 8 + lc;
            uint32_t ahf[4][4], bf[4][2];
#pragma unroll
            for (int mf = 0; mf < 4; mf++) {
                int p = wm + mf * 16 + lr;
                ahf[mf][0] = __float_as_uint(Ah[ka * ASTR + p]);
                ahf[mf][1] = __float_as_uint(Ah[ka * ASTR + p + 8]);
                ahf[mf][2] = __float_as_uint(Ah[(ka + 4) * ASTR + p]);
                ahf[mf][3] = __float_as_uint(Ah[(ka + 4) * ASTR + p + 8]);
            }
#pragma unroll
            for (int nf = 0; nf < 4; nf++) {
                int j = wn + nf * 8 + lr;
                bf[nf][0] = __float_as_uint(Bl[ka * ASTR + j]);
                bf[nf][1] = __float_as_uint(Bl[(ka + 4) * ASTR + j]);
            }
#pragma unroll
            for (int mf = 0; mf < 4; mf++)
#pragma unroll
                for (int nf = 0; nf < 4; nf++) mma8(cacc[mf][nf], ahf[mf], bf[nf]);
        }
    }

    // Store z[j][n]; 32B sectors
#pragma unroll
    for (int mf = 0; mf < 4; mf++) {
        int pix = n0 + wm + mf * 16 + lr;
#pragma unroll
        for (int nf = 0; nf < 4; nf++) {
            int j = j0 + wn + nf * 8 + 2 * lc;
            if (j < MEM_DIM) {
                g_z[(size_t)j * NPIX + pix]           = cacc[mf][nf][0];
                g_z[(size_t)(j + 1) * NPIX + pix]     = cacc[mf][nf][1];
                g_z[(size_t)j * NPIX + pix + 8]       = cacc[mf][nf][2];
                g_z[(size_t)(j + 1) * NPIX + pix + 8] = cacc[mf][nf][3];
            }
        }
    }
}

// ---------------------------------------------------------------------------
// Kernel 2: softmax + shrink + L1-renorm + transposed writes + sparse GEMM2.
// Marginal entries (|we-λ| < 1% λ) get their z recomputed with the exact
// serial-FFMA recurrence of the known-passing R1 kernel (bit-identical).
// ---------------------------------------------------------------------------
#define SMEM_EPI ((MEM_DIM*P + 32*P + P + P + P + P*CAP*2 + P*FEA) * 4)

__global__ void __launch_bounds__(256)
epilogue_kernel(const float* __restrict__ x, const float* __restrict__ Mm,
                float* __restrict__ y, float* __restrict__ att)
{
    extern __shared__ float sm[];
    float* zs     = sm;                       // [2000][P]
    float* red    = sm + MEM_DIM * P;         // [32 groups][P]
    float* denomv = red + 32 * P;             // P
    int*   cnt    = (int*)(denomv + P);       // P
    int*   ovf    = cnt + P;                  // P
    int*   lj     = ovf + P;                  // [P][CAP]
    float* lv     = (float*)(lj + P * CAP);   // [P][CAP]
    float* yt     = lv + P * CAP;             // [P][256]

    const int tid = threadIdx.x;
    const int n0  = blockIdx.x * P;
    const int b   = n0 >> 10;
    const int hw0 = n0 & 1023;

    for (int idx = tid; idx < MEM_DIM * (P / 4); idx += 256) {
        int j = idx >> 1, q = (idx & 1) << 2;
        *(float4*)&zs[j * P + q] = *(const float4*)&g_z[(size_t)j * NPIX + n0 + q];
    }
    if (tid < P) { cnt[tid] = 0; ovf[tid] = 0; }
    __syncthreads();

    const int p = tid & (P - 1);   // pixel
    const int g = tid >> 3;        // group (j-stripe), 32 groups

    // ---- Phase A: row max ----
    float mx = -1e30f;
    for (int j = g; j < MEM_DIM; j += 32) mx = fmaxf(mx, zs[j * P + p]);
    red[g * P + p] = mx;
    __syncthreads();
    for (int s = 16; s > 0; s >>= 1) {
        if (g < s) red[g * P + p] = fmaxf(red[g * P + p], red[(g + s) * P + p]);
        __syncthreads();
    }
    mx = red[p];
    __syncthreads();

    // ---- Phase B: softmax denominator ----
    float sum = 0.f;
    for (int j = g; j < MEM_DIM; j += 32) sum += __expf(zs[j * P + p] - mx);
    red[g * P + p] = sum;
    __syncthreads();
    for (int s = 16; s > 0; s >>= 1) {
        if (g < s) red[g * P + p] += red[(g + s) * P + p];
        __syncthreads();
    }
    const float S = red[p];
    __syncthreads();
    const float invS = 1.f / S;

    // ---- Phase C: hard-shrink + L1 sum; record survivors ----
    float dsum = 0.f;
    for (int j = g; j < MEM_DIM; j += 32) {
        float z = zs[j * P + p];
        float w = __expf(z - mx) * invS;       // fast scan
        float s2 = 0.f;
        if (w > 0.999f * SHRINK) {
            float we = expf(z - mx) / S;       // precise near/above threshold
            if (fabsf(we - SHRINK) < SHRINK * 0.01f) {
                // Marginal: recompute z with R1's exact serial FFMA order
                const float* qp = x + (size_t)b * FEA * HW + hw0 + p;
                const float* mp = Mm + (size_t)j * FEA;
                float acc = 0.f;
                for (int k = 0; k < FEA; k++)
                    acc = fmaf(qp[(size_t)k * HW], mp[k], acc);
                we = expf(acc - mx) / S;
            }
            float d = we - SHRINK;
            if (d > 0.f) {
                s2 = d * we / (d + 1e-12f);
                int id = atomicAdd(&cnt[p], 1);
                if (id < CAP) { lj[p * CAP + id] = j; lv[p * CAP + id] = s2; }
                else ovf[p] = 1;
            }
        }
        zs[j * P + p] = s2;
        dsum += s2;
    }
    red[g * P + p] = dsum;
    __syncthreads();
    for (int s = 16; s > 0; s >>= 1) {
        if (g < s) red[g * P + p] += red[(g + s) * P + p];
        __syncthreads();
    }
    if (tid < P) denomv[tid] = 1.f / fmaxf(red[tid], 1e-12f);
    __syncthreads();

    // ---- Phase D: write att_map[b][j][h][w] ----
    float* attb = att + ((size_t)b * MEM_DIM) * HW + hw0;
    for (int idx = tid; idx < MEM_DIM * (P / 4); idx += 256) {
        int j = idx >> 1, q = (idx & 1) << 2;
        float4 v = *(float4*)&zs[j * P + q];
        v.x *= denomv[q];     v.y *= denomv[q + 1];
        v.z *= denomv[q + 2]; v.w *= denomv[q + 3];
        *(float4*)&attb[(size_t)j * HW + q] = v;
    }

    // ---- Phase E: sparse GEMM2 -> y tile (one warp per pixel) ----
    const int wid = tid >> 5, lane = tid & 31;
    {
        int pp = wid;
        float acc[8] = {0, 0, 0, 0, 0, 0, 0, 0};
        if (!ovf[pp]) {
            int nc = cnt[pp];
            float idn = denomv[pp];
            for (int i = 0; i < nc; i++) {
                int jv = lj[pp * CAP + i];
                float a = lv[pp * CAP + i] * idn;
                const float* mr = Mm + (size_t)jv * FEA;
#pragma unroll
                for (int r = 0; r < 8; r++)
                    acc[r] = fmaf(a, mr[r * 32 + lane], acc[r]);
            }
        }
#pragma unroll
        for (int r = 0; r < 8; r++) yt[pp * 256 + r * 32 + lane] = acc[r];
    }
    __syncthreads();

    // Dense fallback on (statistically impossible) overflow
    for (int pp = 0; pp < P; pp++) {
        if (!ovf[pp]) continue;
        float acc = 0.f;
        int c = tid;
        for (int j = 0; j < MEM_DIM; j++)
            acc = fmaf(zs[j * P + pp], Mm[(size_t)j * FEA + c], acc);
        yt[pp * 256 + c] = acc * denomv[pp];
    }
    __syncthreads();

    // ---- Write y[b][c][h][w] ----
    float* yb = y + ((size_t)b * FEA) * HW + hw0;
    for (int idx = tid; idx < P * FEA; idx += 256) {
        int c = idx >> 3, pp = idx & (P - 1);
        yb[(size_t)c * HW + pp] = yt[pp * 256 + c];
    }
}

// ---------------------------------------------------------------------------
extern "C" void kernel_launch(void* const* d_in, const int* in_sizes, int n_in,
                              void* d_out, int out_size)
{
    const float* x  = (const float*)d_in[0];
    const float* Mm = (const float*)d_in[1];
    if (in_sizes[0] == MEM_DIM * FEA && in_sizes[1] == NPIX * FEA) {
        const float* t = x; x = Mm; Mm = t;
    }

    float* y   = (float*)d_out;
    float* att = (float*)d_out + (size_t)32 * FEA * HW;

    cudaFuncSetAttribute(gemm1_tc,
                         cudaFuncAttributeMaxDynamicSharedMemorySize, GEMM_SMEM);
    dim3 g1(NPIX / 128, (MEM_DIM + 127) / 128);
    gemm1_tc<<<g1, 256, GEMM_SMEM>>>(x, Mm);

    cudaFuncSetAttribute(epilogue_kernel,
                         cudaFuncAttributeMaxDynamicSharedMemorySize, SMEM_EPI);
    epilogue_kernel<<<NPIX / P, 256, SMEM_EPI>>>(x, Mm, y, att);
}

// round 13
// speedup vs baseline: 2.3536x; 2.3536x over previous
#include <cuda_runtime.h>
#include <cuda_fp16.h>
#include <cuda_bf16.h>
#include <math.h>
#include <stdint.h>

#define MEM_DIM 2000
#define FEA     256
#define NPIX    32768
#define HW      1024
#define SHRINK  0.0025f
#define FCAP    512        // flat candidate list capacity per epilogue CTA

// scratch: z as fp16 [j][n] (131 MB) + per-pixel exp-partials [16][n] (2 MB)
__device__ __half g_z[(size_t)MEM_DIM * NPIX];
__device__ float  g_spart[16 * NPIX];

// d.hi = cvt(first src), d.lo = cvt(second src)
__device__ __forceinline__ uint32_t pack_bf16x2(float lo_elt, float hi_elt) {
    uint32_t r;
    asm("cvt.rn.bf16x2.f32 %0, %1, %2;" : "=r"(r) : "f"(hi_elt), "f"(lo_elt));
    return r;
}

__device__ __forceinline__ void mma16(float* c, const uint32_t* a, const uint32_t* b) {
    asm volatile("mma.sync.aligned.m16n8k16.row.col.f32.bf16.bf16.f32 "
        "{%0,%1,%2,%3}, {%4,%5,%6,%7}, {%8,%9}, {%0,%1,%2,%3};"
        : "+f"(c[0]), "+f"(c[1]), "+f"(c[2]), "+f"(c[3])
        : "r"(a[0]), "r"(a[1]), "r"(a[2]), "r"(a[3]), "r"(b[0]), "r"(b[1]));
}

// ---------------------------------------------------------------------------
// GEMM1: z[j][n] = q[n][:]·M[j][:], bf16 3-pass split (hh + hl + lh).
// CTA tile 128 px x 128 j, K=256 in 8 chunks of 32 (2 mma k-steps each).
// Also computes per-pixel sum(exp(z)) partials -> g_spart, and stores z fp16.
// ---------------------------------------------------------------------------
#define MSTR 136                         // u32 stride of packed tiles
#define TILEW (16 * MSTR)                // 2176 words per tile
#define OFF_STG   (4 * TILEW)            // staging [128][33] f32
#define OFF_SPART (OFF_STG + 128 * 33)   // [4][128] f32
#define GEMM_SMEM ((OFF_SPART + 512) * 4)

__global__ void __launch_bounds__(256, 2)
gemm1_tc(const float* __restrict__ x, const float* __restrict__ Mm)
{
    extern __shared__ float sm[];
    uint32_t* Ahu = (uint32_t*)sm;
    uint32_t* Alu = Ahu + TILEW;
    uint32_t* Bhu = Alu + TILEW;
    uint32_t* Blu = Bhu + TILEW;
    float* stg    = sm + OFF_STG;
    float* spart  = sm + OFF_SPART;
    __half* zsm   = (__half*)sm;         // reuses tile region (128*136 halves)

    const int tid  = threadIdx.x;
    const int wid  = tid >> 5;
    const int lane = tid & 31;
    const int lr   = lane >> 2;          // 0..7
    const int lc   = lane & 3;           // 0..3

    const int n0  = blockIdx.x * 128;
    const int j0  = blockIdx.y * 128;
    const int b   = n0 >> 10;
    const int hw0 = n0 & 1023;
    const float* xb = x + (size_t)b * FEA * HW + hw0;

    const int wm = (wid & 1) * 64;
    const int wn = (wid >> 1) * 32;

    float cacc[4][4][4];
#pragma unroll
    for (int mf = 0; mf < 4; mf++)
#pragma unroll
        for (int nf = 0; nf < 4; nf++)
#pragma unroll
            for (int r = 0; r < 4; r++) cacc[mf][nf][r] = 0.f;

    for (int c8 = 0; c8 < 8; c8++) {
        const int k0 = c8 * 32;
        __syncthreads();   // prev chunk's mma done before overwriting tiles

        // A: x k-major -> packed bf16x2 [kk2][p]
#pragma unroll
        for (int it = 0; it < 8; it++) {
            int idx = tid + it * 256;
            int kk2 = idx >> 7, p = idx & 127;
            float v0 = xb[(size_t)(k0 + 2 * kk2) * HW + p];
            float v1 = xb[(size_t)(k0 + 2 * kk2 + 1) * HW + p];
            uint32_t hp = pack_bf16x2(v0, v1);
            float l0 = v0 - __uint_as_float(hp << 16);
            float l1 = v1 - __uint_as_float(hp & 0xFFFF0000u);
            Ahu[kk2 * MSTR + p] = hp;
            Alu[kk2 * MSTR + p] = pack_bf16x2(l0, l1);
        }
        // B staging: M[j][k] coalesced -> stg[j][33]
#pragma unroll
        for (int it = 0; it < 16; it++) {
            int idx = tid + it * 256;
            int r = idx >> 5, cc = idx & 31;
            int j = j0 + r; if (j >= MEM_DIM) j = MEM_DIM - 1;
            stg[r * 33 + cc] = Mm[(size_t)j * FEA + k0 + cc];
        }
        __syncthreads();
        // transpose+split+pack: stg[j][k] -> Bh/Bl[kk2][j]
#pragma unroll
        for (int it = 0; it < 8; it++) {
            int idx = tid + it * 256;
            int kk2 = idx >> 7, jj = idx & 127;
            float v0 = stg[jj * 33 + 2 * kk2];
            float v1 = stg[jj * 33 + 2 * kk2 + 1];
            uint32_t hp = pack_bf16x2(v0, v1);
            float l0 = v0 - __uint_as_float(hp << 16);
            float l1 = v1 - __uint_as_float(hp & 0xFFFF0000u);
            Bhu[kk2 * MSTR + jj] = hp;
            Blu[kk2 * MSTR + jj] = pack_bf16x2(l0, l1);
        }
        __syncthreads();

#pragma unroll
        for (int s = 0; s < 2; s++) {
            const int kb = s * 8;
            uint32_t af[4][4], bh[4][2], bl[4][2];
#pragma unroll
            for (int nf = 0; nf < 4; nf++) {
                int j = wn + nf * 8 + lr;
                bh[nf][0] = Bhu[(kb + lc) * MSTR + j];
                bh[nf][1] = Bhu[(kb + lc + 4) * MSTR + j];
                bl[nf][0] = Blu[(kb + lc) * MSTR + j];
                bl[nf][1] = Blu[(kb + lc + 4) * MSTR + j];
            }
#pragma unroll
            for (int mf = 0; mf < 4; mf++) {
                int p = wm + mf * 16 + lr;
                af[mf][0] = Ahu[(kb + lc) * MSTR + p];
                af[mf][1] = Ahu[(kb + lc) * MSTR + p + 8];
                af[mf][2] = Ahu[(kb + lc + 4) * MSTR + p];
                af[mf][3] = Ahu[(kb + lc + 4) * MSTR + p + 8];
            }
#pragma unroll
            for (int mf = 0; mf < 4; mf++)
#pragma unroll
                for (int nf = 0; nf < 4; nf++) mma16(cacc[mf][nf], af[mf], bh[nf]);
#pragma unroll
            for (int mf = 0; mf < 4; mf++)
#pragma unroll
                for (int nf = 0; nf < 4; nf++) mma16(cacc[mf][nf], af[mf], bl[nf]);
            // reload A-lo into af, do lh
#pragma unroll
            for (int mf = 0; mf < 4; mf++) {
                int p = wm + mf * 16 + lr;
                af[mf][0] = Alu[(kb + lc) * MSTR + p];
                af[mf][1] = Alu[(kb + lc) * MSTR + p + 8];
                af[mf][2] = Alu[(kb + lc + 4) * MSTR + p];
                af[mf][3] = Alu[(kb + lc + 4) * MSTR + p + 8];
            }
#pragma unroll
            for (int mf = 0; mf < 4; mf++)
#pragma unroll
                for (int nf = 0; nf < 4; nf++) mma16(cacc[mf][nf], af[mf], bh[nf]);
        }
    }

    // ---- per-pixel exp partials (from fp32 accumulators, m=0 shift) ----
    float ps[8];
#pragma unroll
    for (int i = 0; i < 8; i++) ps[i] = 0.f;
#pragma unroll
    for (int mf = 0; mf < 4; mf++)
#pragma unroll
        for (int nf = 0; nf < 4; nf++) {
            int j = j0 + wn + nf * 8 + 2 * lc;
            if (j < MEM_DIM) {
                ps[mf * 2 + 0] += __expf(cacc[mf][nf][0]) + __expf(cacc[mf][nf][1]);
                ps[mf * 2 + 1] += __expf(cacc[mf][nf][2]) + __expf(cacc[mf][nf][3]);
            }
        }
#pragma unroll
    for (int i = 0; i < 8; i++) {
        ps[i] += __shfl_xor_sync(0xffffffffu, ps[i], 1);
        ps[i] += __shfl_xor_sync(0xffffffffu, ps[i], 2);
    }
    if (lc == 0) {
        int jw = wid >> 1;
#pragma unroll
        for (int mf = 0; mf < 4; mf++) {
            spart[jw * 128 + wm + mf * 16 + lr]     = ps[mf * 2 + 0];
            spart[jw * 128 + wm + mf * 16 + lr + 8] = ps[mf * 2 + 1];
        }
    }
    __syncthreads();   // also guarantees all mma done before zsm overwrite
    if (tid < 128) {
        float s = spart[tid] + spart[128 + tid] + spart[256 + tid] + spart[384 + tid];
        g_spart[(size_t)blockIdx.y * NPIX + n0 + tid] = s;
    }

    // ---- stage z fp16 in smem, then coalesced store ----
#pragma unroll
    for (int mf = 0; mf < 4; mf++) {
        int p = wm + mf * 16 + lr;
#pragma unroll
        for (int nf = 0; nf < 4; nf++) {
            int jj = wn + nf * 8 + 2 * lc;
            zsm[jj * 136 + p]           = __float2half_rn(cacc[mf][nf][0]);
            zsm[(jj + 1) * 136 + p]     = __float2half_rn(cacc[mf][nf][1]);
            zsm[jj * 136 + p + 8]       = __float2half_rn(cacc[mf][nf][2]);
            zsm[(jj + 1) * 136 + p + 8] = __float2half_rn(cacc[mf][nf][3]);
        }
    }
    __syncthreads();
#pragma unroll
    for (int it = 0; it < 8; it++) {
        int idx = tid + it * 256;
        int row = idx >> 4, q = (idx & 15) * 8;
        int j = j0 + row;
        if (j < MEM_DIM)
            *(uint4*)&g_z[(size_t)j * NPIX + n0 + q] = *(uint4*)&zsm[row * 136 + q];
    }
}

// ---------------------------------------------------------------------------
// Epilogue: per 16-pixel CTA. No softmax reductions (S precomputed).
// fp16-z scan -> candidate list -> exact recompute (warp per candidate) ->
// att zero-fill + sparse scatter, sparse y.
// ---------------------------------------------------------------------------
#define XSTR 257
// word offsets
#define W_ZS   0                      // 16000 words (2000*16 half)
#define W_XT   16000                  // 16*257 = 4112
#define W_SV   (W_XT + 4112)          // 16
#define W_DNM  (W_SV + 16)            // 16
#define W_TOT  (W_DNM + 16)           // 1
#define W_OVF  (W_TOT + 1)            // 1 (+pad)
#define W_CPJ  (W_TOT + 16)           // FCAP
#define W_CV   (W_CPJ + FCAP)         // FCAP
#define W_YT   (W_CV + FCAP)          // 4096
#define SMEM_EPI ((W_YT + 4096) * 4)

__global__ void __launch_bounds__(256, 2)
epilogue_kernel(const float* __restrict__ x, const float* __restrict__ Mm,
                float* __restrict__ y, float* __restrict__ att)
{
    extern __shared__ float sm[];
    __half* zs = (__half*)sm;
    float* xt  = sm + W_XT;
    float* Sv  = sm + W_SV;
    float* dnm = sm + W_DNM;
    int*   tot = (int*)(sm + W_TOT);
    int*   ovf = (int*)(sm + W_OVF);
    int*   cpj = (int*)(sm + W_CPJ);
    float* cv  = sm + W_CV;
    float* yt  = sm + W_YT;

    const int tid = threadIdx.x;
    const int n0  = blockIdx.x * 16;
    const int b   = n0 >> 10;
    const int hw0 = n0 & 1023;
    float* attb = att + ((size_t)b * MEM_DIM) * HW + hw0;

    // z tile (fp16, 32B per j-row)
#pragma unroll 4
    for (int idx = tid; idx < MEM_DIM * 2; idx += 256) {
        int j = idx >> 1, q = (idx & 1) * 8;
        *(uint4*)&zs[j * 16 + q] = *(const uint4*)&g_z[(size_t)j * NPIX + n0 + q];
    }
    // x tile [p][k] for exact recompute
#pragma unroll 4
    for (int idx = tid; idx < FEA * 16; idx += 256) {
        int k = idx >> 4, p2 = idx & 15;
        xt[p2 * XSTR + k] = x[(size_t)b * FEA * HW + (size_t)k * HW + hw0 + p2];
    }
    // att zero-fill (streaming, independent)
    const float4 z4 = make_float4(0.f, 0.f, 0.f, 0.f);
#pragma unroll 4
    for (int idx = tid; idx < MEM_DIM * 4; idx += 256) {
        int j = idx >> 2, q = (idx & 3) * 4;
        *(float4*)&attb[(size_t)j * HW + q] = z4;
    }
    if (tid < 16) {
        float s = 0.f;
#pragma unroll
        for (int jb = 0; jb < 16; jb++) s += g_spart[(size_t)jb * NPIX + n0 + tid];
        Sv[tid]  = s;
        dnm[tid] = 0.f;
    }
    if (tid == 0) { *tot = 0; *ovf = 0; }
    __syncthreads();

    const int p = tid & 15;
    const int g = tid >> 4;
    const float invS = 1.f / Sv[p];

    // ---- scan: push candidates (fp16 z, band 0.995λ) ----
    for (int j = g; j < MEM_DIM; j += 16) {
        float zf = __half2float(zs[j * 16 + p]);
        if (__expf(zf) * invS > 0.995f * SHRINK) {
            int e = atomicAdd(tot, 1);
            if (e < FCAP) cpj[e] = (p << 16) | j;
            else *ovf = 1;
        }
    }
    __syncthreads();
    const int T = min(*tot, FCAP);
    const int wwid = tid >> 5, wlane = tid & 31;

    // ---- resolve: exact z (fp32, warp per candidate), precise exp/S ----
    for (int e = wwid; e < T; e += 8) {
        int pj = cpj[e];
        int p2 = pj >> 16, j = pj & 0xffff;
        const float* mr = Mm + (size_t)j * FEA;
        float a = 0.f;
#pragma unroll
        for (int kk = 0; kk < 8; kk++) {
            int k = kk * 32 + wlane;
            a = fmaf(xt[p2 * XSTR + k], mr[k], a);
        }
#pragma unroll
        for (int d = 16; d > 0; d >>= 1) a += __shfl_xor_sync(0xffffffffu, a, d);
        if (wlane == 0) {
            float we = expf(a) / Sv[p2];
            float d2 = we - SHRINK;
            cv[e] = (d2 > 0.f) ? d2 * we / (d2 + 1e-12f) : 0.f;
        }
    }
    __syncthreads();

    const int is_ovf = *ovf;
    if (!is_ovf) {
        // denom per pixel
        for (int e = tid; e < T; e += 256)
            atomicAdd(&dnm[cpj[e] >> 16], cv[e]);
        __syncthreads();
        if (tid < 16) dnm[tid] = 1.f / fmaxf(dnm[tid], 1e-12f);
        __syncthreads();
        // sparse att scatter
        for (int e = tid; e < T; e += 256) {
            int p2 = cpj[e] >> 16, j = cpj[e] & 0xffff;
            attb[(size_t)j * HW + p2] = cv[e] * dnm[p2];
        }
        // sparse y -> yt (warp per pixel)
        for (int pp = wwid; pp < 16; pp += 8) {
            float acc[8] = {0, 0, 0, 0, 0, 0, 0, 0};
            float idn = dnm[pp];
            for (int e = 0; e < T; e++) {
                if ((cpj[e] >> 16) != pp) continue;
                float aval = cv[e] * idn;
                const float* mr = Mm + (size_t)(cpj[e] & 0xffff) * FEA;
#pragma unroll
                for (int r = 0; r < 8; r++)
                    acc[r] = fmaf(aval, mr[r * 32 + wlane], acc[r]);
            }
#pragma unroll
            for (int r = 0; r < 8; r++) yt[pp * 256 + r * 32 + wlane] = acc[r];
        }
    } else {
        // Degraded dense fallback (statistically unreachable): fp16-z values.
        float ds = 0.f;
        for (int j = g; j < MEM_DIM; j += 16) {
            float we = expf(__half2float(zs[j * 16 + p])) / Sv[p];
            float d2 = we - SHRINK;
            ds += (d2 > 0.f) ? d2 * we / (d2 + 1e-12f) : 0.f;
        }
        atomicAdd(&dnm[p], ds);
        __syncthreads();
        if (tid < 16) dnm[tid] = 1.f / fmaxf(dnm[tid], 1e-12f);
        __syncthreads();
        for (int j = g; j < MEM_DIM; j += 16) {
            float we = expf(__half2float(zs[j * 16 + p])) / Sv[p];
            float d2 = we - SHRINK;
            float s2 = (d2 > 0.f) ? d2 * we / (d2 + 1e-12f) * dnm[p] : 0.f;
            attb[(size_t)j * HW + p] = s2;
        }
        for (int pp = wwid; pp < 16; pp += 8) {
            float acc[8] = {0, 0, 0, 0, 0, 0, 0, 0};
            for (int j = 0; j < MEM_DIM; j++) {
                float we = expf(__half2float(zs[j * 16 + pp])) / Sv[pp];
                float d2 = we - SHRINK;
                if (d2 > 0.f) {
                    float aval = d2 * we / (d2 + 1e-12f) * dnm[pp];
                    const float* mr = Mm + (size_t)j * FEA;
#pragma unroll
                    for (int r = 0; r < 8; r++)
                        acc[r] = fmaf(aval, mr[r * 32 + wlane], acc[r]);
                }
            }
#pragma unroll
            for (int r = 0; r < 8; r++) yt[pp * 256 + r * 32 + wlane] = acc[r];
        }
    }
    __syncthreads();

    // y[b][c][h][w], 64B per c-row
    float* yb = y + ((size_t)b * FEA) * HW + hw0;
#pragma unroll 4
    for (int idx = tid; idx < 16 * FEA; idx += 256) {
        int c = idx >> 4, pp = idx & 15;
        yb[(size_t)c * HW + pp] = yt[pp * 256 + c];
    }
}

// ---------------------------------------------------------------------------
extern "C" void kernel_launch(void* const* d_in, const int* in_sizes, int n_in,
                              void* d_out, int out_size)
{
    const float* x  = (const float*)d_in[0];
    const float* Mm = (const float*)d_in[1];
    if (in_sizes[0] == MEM_DIM * FEA && in_sizes[1] == NPIX * FEA) {
        const float* t = x; x = Mm; Mm = t;
    }

    float* y   = (float*)d_out;
    float* att = (float*)d_out + (size_t)32 * FEA * HW;

    cudaFuncSetAttribute(gemm1_tc,
                         cudaFuncAttributeMaxDynamicSharedMemorySize, GEMM_SMEM);
    dim3 g1(NPIX / 128, 16);
    gemm1_tc<<<g1, 256, GEMM_SMEM>>>(x, Mm);

    cudaFuncSetAttribute(epilogue_kernel,
                         cudaFuncAttributeMaxDynamicSharedMemorySize, SMEM_EPI);
    epilogue_kernel<<<NPIX / 16, 256, SMEM_EPI>>>(x, Mm, y, att);
}

// round 14
// speedup vs baseline: 2.7073x; 1.1503x over previous
#include <cuda_runtime.h>
#include <cuda_fp16.h>
#include <cuda_bf16.h>
#include <math.h>
#include <stdint.h>

#define MEM_DIM 2000
#define FEA     256
#define NPIX    32768
#define HW      1024
#define SHRINK  0.0025f
#define NGRP    2048       // pixel groups of 16
#define CAP2    1024       // candidate capacity per group
#define SCAP    256        // survivor capacity per group
#define CCAP    512        // shortlist capacity per group
#define Z_PUSH  1.376f     // ln(0.99 * SHRINK * 1600); S is provably >= 2100

// scratch: candidate lists (16.8 MB) + counters + per-pixel exp-partials (2 MB)
__device__ uint2 g_cand[(size_t)NGRP * CAP2];
__device__ int   g_cnt[NGRP];
__device__ float g_spart[16 * NPIX];

// d.hi = cvt(first src), d.lo = cvt(second src)
__device__ __forceinline__ uint32_t pack_bf16x2(float lo_elt, float hi_elt) {
    uint32_t r;
    asm("cvt.rn.bf16x2.f32 %0, %1, %2;" : "=r"(r) : "f"(hi_elt), "f"(lo_elt));
    return r;
}

__device__ __forceinline__ void mma16(float* c, const uint32_t* a, const uint32_t* b) {
    asm volatile("mma.sync.aligned.m16n8k16.row.col.f32.bf16.bf16.f32 "
        "{%0,%1,%2,%3}, {%4,%5,%6,%7}, {%8,%9}, {%0,%1,%2,%3};"
        : "+f"(c[0]), "+f"(c[1]), "+f"(c[2]), "+f"(c[3])
        : "r"(a[0]), "r"(a[1]), "r"(a[2]), "r"(a[3]), "r"(b[0]), "r"(b[1]));
}

__global__ void zero_cnt_kernel() {
    int i = blockIdx.x * 256 + threadIdx.x;
    if (i < NGRP) g_cnt[i] = 0;
}

// ---------------------------------------------------------------------------
// GEMM1: z[j][n] = q[n][:]·M[j][:], bf16 3-pass split (hh + hl + lh).
// CTA tile 128 px x 128 j, K=256 in 8 chunks of 32.
// Outputs: per-pixel exp-sum partials (g_spart) + candidate pushes (g_cand).
// No z array at all.
// ---------------------------------------------------------------------------
#define MSTR 136                         // u32 stride of packed tiles
#define TILEW (16 * MSTR)                // 2176 words per tile
#define OFF_STG   (4 * TILEW)            // staging [128][33] f32
#define OFF_SPART (OFF_STG + 128 * 33)   // [4][128] f32
#define GEMM_SMEM ((OFF_SPART + 512) * 4)

__global__ void __launch_bounds__(256, 2)
gemm1_tc(const float* __restrict__ x, const float* __restrict__ Mm)
{
    extern __shared__ float sm[];
    uint32_t* Ahu = (uint32_t*)sm;
    uint32_t* Alu = Ahu + TILEW;
    uint32_t* Bhu = Alu + TILEW;
    uint32_t* Blu = Bhu + TILEW;
    float* stg    = sm + OFF_STG;
    float* spart  = sm + OFF_SPART;

    const int tid  = threadIdx.x;
    const int wid  = tid >> 5;
    const int lane = tid & 31;
    const int lr   = lane >> 2;          // 0..7
    const int lc   = lane & 3;           // 0..3

    const int n0  = blockIdx.x * 128;
    const int j0  = blockIdx.y * 128;
    const int b   = n0 >> 10;
    const int hw0 = n0 & 1023;
    const float* xb = x + (size_t)b * FEA * HW + hw0;

    const int wm = (wid & 1) * 64;
    const int wn = (wid >> 1) * 32;

    float cacc[4][4][4];
#pragma unroll
    for (int mf = 0; mf < 4; mf++)
#pragma unroll
        for (int nf = 0; nf < 4; nf++)
#pragma unroll
            for (int r = 0; r < 4; r++) cacc[mf][nf][r] = 0.f;

    for (int c8 = 0; c8 < 8; c8++) {
        const int k0 = c8 * 32;
        __syncthreads();   // prev chunk's mma done before overwriting tiles

        // A: x k-major -> packed bf16x2 [kk2][p]
#pragma unroll
        for (int it = 0; it < 8; it++) {
            int idx = tid + it * 256;
            int kk2 = idx >> 7, p = idx & 127;
            float v0 = xb[(size_t)(k0 + 2 * kk2) * HW + p];
            float v1 = xb[(size_t)(k0 + 2 * kk2 + 1) * HW + p];
            uint32_t hp = pack_bf16x2(v0, v1);
            float l0 = v0 - __uint_as_float(hp << 16);
            float l1 = v1 - __uint_as_float(hp & 0xFFFF0000u);
            Ahu[kk2 * MSTR + p] = hp;
            Alu[kk2 * MSTR + p] = pack_bf16x2(l0, l1);
        }
        // B staging: M[j][k] coalesced -> stg[j][33]
#pragma unroll
        for (int it = 0; it < 16; it++) {
            int idx = tid + it * 256;
            int r = idx >> 5, cc = idx & 31;
            int j = j0 + r; if (j >= MEM_DIM) j = MEM_DIM - 1;
            stg[r * 33 + cc] = Mm[(size_t)j * FEA + k0 + cc];
        }
        __syncthreads();
        // transpose+split+pack: stg[j][k] -> Bh/Bl[kk2][j]
#pragma unroll
        for (int it = 0; it < 8; it++) {
            int idx = tid + it * 256;
            int kk2 = idx >> 7, jj = idx & 127;
            float v0 = stg[jj * 33 + 2 * kk2];
            float v1 = stg[jj * 33 + 2 * kk2 + 1];
            uint32_t hp = pack_bf16x2(v0, v1);
            float l0 = v0 - __uint_as_float(hp << 16);
            float l1 = v1 - __uint_as_float(hp & 0xFFFF0000u);
            Bhu[kk2 * MSTR + jj] = hp;
            Blu[kk2 * MSTR + jj] = pack_bf16x2(l0, l1);
        }
        __syncthreads();

#pragma unroll
        for (int s = 0; s < 2; s++) {
            const int kb = s * 8;
            uint32_t af[4][4], bh[4][2], bl[4][2];
#pragma unroll
            for (int nf = 0; nf < 4; nf++) {
                int j = wn + nf * 8 + lr;
                bh[nf][0] = Bhu[(kb + lc) * MSTR + j];
                bh[nf][1] = Bhu[(kb + lc + 4) * MSTR + j];
                bl[nf][0] = Blu[(kb + lc) * MSTR + j];
                bl[nf][1] = Blu[(kb + lc + 4) * MSTR + j];
            }
#pragma unroll
            for (int mf = 0; mf < 4; mf++) {
                int p = wm + mf * 16 + lr;
                af[mf][0] = Ahu[(kb + lc) * MSTR + p];
                af[mf][1] = Ahu[(kb + lc) * MSTR + p + 8];
                af[mf][2] = Ahu[(kb + lc + 4) * MSTR + p];
                af[mf][3] = Ahu[(kb + lc + 4) * MSTR + p + 8];
            }
#pragma unroll
            for (int mf = 0; mf < 4; mf++)
#pragma unroll
                for (int nf = 0; nf < 4; nf++) mma16(cacc[mf][nf], af[mf], bh[nf]);
#pragma unroll
            for (int mf = 0; mf < 4; mf++)
#pragma unroll
                for (int nf = 0; nf < 4; nf++) mma16(cacc[mf][nf], af[mf], bl[nf]);
            // reload A-lo into af, do lh
#pragma unroll
            for (int mf = 0; mf < 4; mf++) {
                int p = wm + mf * 16 + lr;
                af[mf][0] = Alu[(kb + lc) * MSTR + p];
                af[mf][1] = Alu[(kb + lc) * MSTR + p + 8];
                af[mf][2] = Alu[(kb + lc + 4) * MSTR + p];
                af[mf][3] = Alu[(kb + lc + 4) * MSTR + p + 8];
            }
#pragma unroll
            for (int mf = 0; mf < 4; mf++)
#pragma unroll
                for (int nf = 0; nf < 4; nf++) mma16(cacc[mf][nf], af[mf], bh[nf]);
        }
    }

    // ---- per-pixel exp partials (from fp32 accumulators, m=0 shift) ----
    float ps[8];
#pragma unroll
    for (int i = 0; i < 8; i++) ps[i] = 0.f;
#pragma unroll
    for (int mf = 0; mf < 4; mf++)
#pragma unroll
        for (int nf = 0; nf < 4; nf++) {
            int j = j0 + wn + nf * 8 + 2 * lc;
            if (j < MEM_DIM) {
                ps[mf * 2 + 0] += __expf(cacc[mf][nf][0]) + __expf(cacc[mf][nf][1]);
                ps[mf * 2 + 1] += __expf(cacc[mf][nf][2]) + __expf(cacc[mf][nf][3]);
            }
        }
#pragma unroll
    for (int i = 0; i < 8; i++) {
        ps[i] += __shfl_xor_sync(0xffffffffu, ps[i], 1);
        ps[i] += __shfl_xor_sync(0xffffffffu, ps[i], 2);
    }
    if (lc == 0) {
        int jw = wid >> 1;
#pragma unroll
        for (int mf = 0; mf < 4; mf++) {
            spart[jw * 128 + wm + mf * 16 + lr]     = ps[mf * 2 + 0];
            spart[jw * 128 + wm + mf * 16 + lr + 8] = ps[mf * 2 + 1];
        }
    }

    // ---- candidate push (z > Z_PUSH covers every possible survivor) ----
#pragma unroll
    for (int mf = 0; mf < 4; mf++) {
#pragma unroll
        for (int nf = 0; nf < 4; nf++) {
            int j = j0 + wn + nf * 8 + 2 * lc;
            if (j >= MEM_DIM) continue;   // j even, MEM_DIM even: j+1 also OK
#pragma unroll
            for (int r = 0; r < 4; r++) {
                float z = cacc[mf][nf][r];
                if (z > Z_PUSH) {
                    int pix = wm + mf * 16 + lr + ((r >> 1) << 3);
                    int jj  = j + (r & 1);
                    int n   = n0 + pix;
                    int grp = n >> 4;
                    int id = atomicAdd(&g_cnt[grp], 1);
                    if (id < CAP2)
                        g_cand[(size_t)grp * CAP2 + id] =
                            make_uint2((uint32_t)(((n & 15) << 16) | jj),
                                       __float_as_uint(z));
                }
            }
        }
    }

    __syncthreads();
    if (tid < 128) {
        float s = spart[tid] + spart[128 + tid] + spart[256 + tid] + spart[384 + tid];
        g_spart[(size_t)blockIdx.y * NPIX + n0 + tid] = s;
    }
}

// ---------------------------------------------------------------------------
// Epilogue: per 16-pixel group. Reads candidate list (no z array, no scan):
// coarse filter with exact S -> warp-exact recompute -> decisions ->
// att zero-fill + sparse scatter, sparse y. 37 KB smem -> high occupancy.
// ---------------------------------------------------------------------------
#define XSTR 257
#define W_XT   0                       // 16*257 = 4112
#define W_SV   (W_XT + 4112)           // 16
#define W_DNM  (W_SV + 16)             // 16
#define W_TOT  (W_DNM + 16)            // 1
#define W_NS   (W_TOT + 1)             // 1
#define W_OVF  (W_NS + 1)              // 1 (+pad to 8)
#define W_CL   (W_TOT + 8)             // CCAP ints
#define W_SMT  (W_CL + CCAP)           // SCAP ints
#define W_SVL  (W_SMT + SCAP)          // SCAP floats
#define W_YT   (W_SVL + SCAP)          // 4096
#define SMEM_EPI ((W_YT + 4096) * 4)

__global__ void __launch_bounds__(256)
epilogue_kernel(const float* __restrict__ x, const float* __restrict__ Mm,
                float* __restrict__ y, float* __restrict__ att)
{
    extern __shared__ float sm[];
    float* xt   = sm + W_XT;
    float* Sv   = sm + W_SV;
    float* dnm  = sm + W_DNM;
    int*   tot  = (int*)(sm + W_TOT);
    int*   ns   = (int*)(sm + W_NS);
    int*   povf = (int*)(sm + W_OVF);
    int*   clist = (int*)(sm + W_CL);
    int*   smt  = (int*)(sm + W_SMT);
    float* svl  = sm + W_SVL;
    float* yt   = sm + W_YT;

    const int tid = threadIdx.x;
    const int grp = blockIdx.x;
    const int n0  = grp * 16;
    const int b   = n0 >> 10;
    const int hw0 = n0 & 1023;
    float* attb = att + ((size_t)b * MEM_DIM) * HW + hw0;

    if (tid == 0) { *tot = 0; *ns = 0; *povf = 0; }
    if (tid < 16) {
        float s = 0.f;
#pragma unroll
        for (int jb = 0; jb < 16; jb++) s += g_spart[(size_t)jb * NPIX + n0 + tid];
        Sv[tid]  = s;
        dnm[tid] = 0.f;
    }
    // x tile [p][k] for exact recompute
#pragma unroll 4
    for (int idx = tid; idx < FEA * 16; idx += 256) {
        int k = idx >> 4, p2 = idx & 15;
        xt[p2 * XSTR + k] = x[(size_t)b * FEA * HW + (size_t)k * HW + hw0 + p2];
    }
    // att zero-fill (this CTA's [MEM_DIM x 16] slab)
    const float4 z4 = make_float4(0.f, 0.f, 0.f, 0.f);
#pragma unroll 4
    for (int idx = tid; idx < MEM_DIM * 4; idx += 256) {
        int j = idx >> 2, q = (idx & 3) * 4;
        *(float4*)&attb[(size_t)j * HW + q] = z4;
    }
    __syncthreads();

    const int cnt  = g_cnt[grp];
    const uint2* cand = g_cand + (size_t)grp * CAP2;
    const int wwid = tid >> 5, wlane = tid & 31;

    if (cnt <= CAP2) {
        // coarse filter with exact S (pushed z is fp32-split, err ~2e-6)
        for (int e = tid; e < cnt; e += 256) {
            uint2 rec = cand[e];
            int p2 = rec.x >> 16;
            float z = __uint_as_float(rec.y);
            if (__expf(z) > 0.9f * SHRINK * Sv[p2]) {
                int id = atomicAdd(tot, 1);
                if (id < CCAP) clist[id] = (int)rec.x;
                else *povf = 1;
            }
        }
        __syncthreads();
    }

    if (cnt > CAP2 || *povf) {
        // dense exact fallback (statistically unreachable): every (p,j) pair
        for (int t = wwid; t < 16 * MEM_DIM; t += 8) {
            int p2 = t & 15, j = t >> 4;
            const float* mr = Mm + (size_t)j * FEA;
            float a = 0.f;
#pragma unroll
            for (int kk = 0; kk < 8; kk++) {
                int k = kk * 32 + wlane;
                a = fmaf(xt[p2 * XSTR + k], mr[k], a);
            }
#pragma unroll
            for (int d = 16; d > 0; d >>= 1) a += __shfl_xor_sync(0xffffffffu, a, d);
            if (wlane == 0) {
                float we = expf(a) / Sv[p2];
                float d2 = we - SHRINK;
                if (d2 > 0.f) {
                    int id = atomicAdd(ns, 1);
                    if (id < SCAP) {
                        smt[id] = (p2 << 16) | j;
                        svl[id] = d2 * we / (d2 + 1e-12f);
                    }
                }
            }
        }
    } else {
        // warp-exact recompute of shortlist, precise decide
        const int T = min(*tot, CCAP);
        for (int e = wwid; e < T; e += 8) {
            int meta = clist[e];
            int p2 = meta >> 16, j = meta & 0xffff;
            const float* mr = Mm + (size_t)j * FEA;
            float a = 0.f;
#pragma unroll
            for (int kk = 0; kk < 8; kk++) {
                int k = kk * 32 + wlane;
                a = fmaf(xt[p2 * XSTR + k], mr[k], a);
            }
#pragma unroll
            for (int d = 16; d > 0; d >>= 1) a += __shfl_xor_sync(0xffffffffu, a, d);
            if (wlane == 0) {
                float we = expf(a) / Sv[p2];
                float d2 = we - SHRINK;
                if (d2 > 0.f) {
                    int id = atomicAdd(ns, 1);
                    if (id < SCAP) {
                        smt[id] = meta;
                        svl[id] = d2 * we / (d2 + 1e-12f);
                    }
                }
            }
        }
    }
    __syncthreads();

    const int NS = min(*ns, SCAP);
    // denom per pixel
    for (int e = tid; e < NS; e += 256) atomicAdd(&dnm[smt[e] >> 16], svl[e]);
    __syncthreads();
    if (tid < 16) dnm[tid] = 1.f / fmaxf(dnm[tid], 1e-12f);
    __syncthreads();

    // sparse att scatter (slab already zeroed by this CTA)
    for (int e = tid; e < NS; e += 256) {
        int p2 = smt[e] >> 16, j = smt[e] & 0xffff;
        attb[(size_t)j * HW + p2] = svl[e] * dnm[p2];
    }

    // sparse y -> yt (warp per pixel)
    for (int pp = wwid; pp < 16; pp += 8) {
        float acc[8] = {0, 0, 0, 0, 0, 0, 0, 0};
        float idn = dnm[pp];
        for (int e = 0; e < NS; e++) {
            if ((smt[e] >> 16) != pp) continue;
            float aval = svl[e] * idn;
            const float* mr = Mm + (size_t)(smt[e] & 0xffff) * FEA;
#pragma unroll
            for (int r = 0; r < 8; r++)
                acc[r] = fmaf(aval, mr[r * 32 + wlane], acc[r]);
        }
#pragma unroll
        for (int r = 0; r < 8; r++) yt[pp * 256 + r * 32 + wlane] = acc[r];
    }
    __syncthreads();

    // y[b][c][h][w], 64B per c-row
    float* yb = y + ((size_t)b * FEA) * HW + hw0;
#pragma unroll 4
    for (int idx = tid; idx < 16 * FEA; idx += 256) {
        int c = idx >> 4, pp = idx & 15;
        yb[(size_t)c * HW + pp] = yt[pp * 256 + c];
    }
}

// ---------------------------------------------------------------------------
extern "C" void kernel_launch(void* const* d_in, const int* in_sizes, int n_in,
                              void* d_out, int out_size)
{
    const float* x  = (const float*)d_in[0];
    const float* Mm = (const float*)d_in[1];
    if (in_sizes[0] == MEM_DIM * FEA && in_sizes[1] == NPIX * FEA) {
        const float* t = x; x = Mm; Mm = t;
    }

    float* y   = (float*)d_out;
    float* att = (float*)d_out + (size_t)32 * FEA * HW;

    zero_cnt_kernel<<<NGRP / 256, 256>>>();

    cudaFuncSetAttribute(gemm1_tc,
                         cudaFuncAttributeMaxDynamicSharedMemorySize, GEMM_SMEM);
    dim3 g1(NPIX / 128, 16);
    gemm1_tc<<<g1, 256, GEMM_SMEM>>>(x, Mm);

    cudaFuncSetAttribute(epilogue_kernel,
                         cudaFuncAttributeMaxDynamicSharedMemorySize, SMEM_EPI);
    epilogue_kernel<<<NGRP, 256, SMEM_EPI>>>(x, Mm, y, att);
}

// round 15
// speedup vs baseline: 3.4848x; 1.2872x over previous
#include <cuda_runtime.h>
#include <cuda_fp16.h>
#include <cuda_bf16.h>
#include <math.h>
#include <stdint.h>

#define MEM_DIM 2000
#define FEA     256
#define NPIX    32768
#define HW      1024
#define SHRINK  0.0025f
#define NGRP    2048       // pixel groups of 16
#define CAP2    1024       // candidate capacity per group
#define SCAP    256        // survivor capacity per group
#define CCAP    512        // shortlist capacity per group
#define Z_PUSH  1.376f     // ln(0.99 * SHRINK * 1600); S is provably >= 2100
#define BJP     2048       // j pitch of packed B arrays

// packed bf16-pair operands (prologue output)
__device__ uint32_t g_Ah[(size_t)128 * NPIX];
__device__ uint32_t g_Al[(size_t)128 * NPIX];
__device__ uint32_t g_Bh[(size_t)128 * BJP];
__device__ uint32_t g_Bl[(size_t)128 * BJP];
// candidate lists + counters + per-pixel exp partials
__device__ uint2 g_cand[(size_t)NGRP * CAP2];
__device__ int   g_cnt[NGRP];
__device__ float g_spart[16 * NPIX];

__device__ __forceinline__ uint32_t smem_u32(const void* p) {
    uint32_t a;
    asm("{ .reg .u64 t; cvta.to.shared.u64 t, %1; cvt.u32.u64 %0, t; }"
        : "=r"(a) : "l"(p));
    return a;
}
// d.hi = cvt(first src), d.lo = cvt(second src)
__device__ __forceinline__ uint32_t pack_bf16x2(float lo_elt, float hi_elt) {
    uint32_t r;
    asm("cvt.rn.bf16x2.f32 %0, %1, %2;" : "=r"(r) : "f"(hi_elt), "f"(lo_elt));
    return r;
}
__device__ __forceinline__ void mma16(float* c, const uint32_t* a, const uint32_t* b) {
    asm volatile("mma.sync.aligned.m16n8k16.row.col.f32.bf16.bf16.f32 "
        "{%0,%1,%2,%3}, {%4,%5,%6,%7}, {%8,%9}, {%0,%1,%2,%3};"
        : "+f"(c[0]), "+f"(c[1]), "+f"(c[2]), "+f"(c[3])
        : "r"(a[0]), "r"(a[1]), "r"(a[2]), "r"(a[3]), "r"(b[0]), "r"(b[1]));
}
#define CP_ASYNC16(sa, g) \
    asm volatile("cp.async.ca.shared.global [%0], [%1], 16;" :: "r"(sa), "l"(g))
#define CP_COMMIT()  asm volatile("cp.async.commit_group;" ::: "memory")
#define CP_WAIT0()   asm volatile("cp.async.wait_group 0;" ::: "memory")

__global__ void zero_cnt_kernel() {
    int i = blockIdx.x * 256 + threadIdx.x;
    if (i < NGRP) g_cnt[i] = 0;
}

// ---------------------------------------------------------------------------
// Prologue A: x[k][n] -> packed bf16 hi/lo pair arrays [k2][n]
// ---------------------------------------------------------------------------
__global__ void split_a_kernel(const float* __restrict__ x)
{
    int n  = blockIdx.x * 256 + threadIdx.x;   // grid.x = 128
    int k2 = blockIdx.y;                       // 128
    int b = n >> 10, hw = n & 1023;
    const float* xp = x + (size_t)b * FEA * HW + (size_t)(2 * k2) * HW + hw;
    float v0 = xp[0], v1 = xp[HW];
    uint32_t hp = pack_bf16x2(v0, v1);
    float l0 = v0 - __uint_as_float(hp << 16);
    float l1 = v1 - __uint_as_float(hp & 0xFFFF0000u);
    g_Ah[(size_t)k2 * NPIX + n] = hp;
    g_Al[(size_t)k2 * NPIX + n] = pack_bf16x2(l0, l1);
}

// ---------------------------------------------------------------------------
// Prologue B: M[j][k] -> packed bf16 hi/lo pair arrays [k2][j]
// ---------------------------------------------------------------------------
__global__ void split_b_kernel(const float* __restrict__ Mm)
{
    int idx = blockIdx.x * 256 + threadIdx.x;  // MEM_DIM*128 total
    if (idx >= MEM_DIM * 128) return;
    int j = idx >> 7, k2 = idx & 127;
    float v0 = Mm[(size_t)j * FEA + 2 * k2];
    float v1 = Mm[(size_t)j * FEA + 2 * k2 + 1];
    uint32_t hp = pack_bf16x2(v0, v1);
    float l0 = v0 - __uint_as_float(hp << 16);
    float l1 = v1 - __uint_as_float(hp & 0xFFFF0000u);
    g_Bh[(size_t)k2 * BJP + j] = hp;
    g_Bl[(size_t)k2 * BJP + j] = pack_bf16x2(l0, l1);
}

// ---------------------------------------------------------------------------
// GEMM1: z[j][n] = q[n][:]·M[j][:], bf16 3-pass split (hh + hl + lh).
// Pre-packed operands, cp.async double-buffered stages, one sync per chunk.
// Outputs: exp-sum partials (g_spart) + candidate pushes (g_cand). No z array.
// ---------------------------------------------------------------------------
#define MSTR  136                          // u32 stride inside a tile
#define TILEW (16 * MSTR)                  // 2176 words per tile
#define TILE_BYTES (TILEW * 4)             // 8704
#define STAGE_W (4 * TILEW)                // words per stage (Ah Al Bh Bl)
#define OFF_SPART (2 * STAGE_W)            // [4][128] f32
#define GEMM_SMEM ((OFF_SPART + 512) * 4)

__global__ void __launch_bounds__(256, 2)
gemm1_tc(const float* __restrict__ x, const float* __restrict__ Mm)
{
    extern __shared__ float sm[];
    const uint32_t sbase = smem_u32(sm);
    float* spart = sm + OFF_SPART;

    const int tid  = threadIdx.x;
    const int wid  = tid >> 5;
    const int lane = tid & 31;
    const int lr   = lane >> 2;            // 0..7
    const int lc   = lane & 3;             // 0..3

    const int n0 = blockIdx.x * 128;
    const int j0 = blockIdx.y * 128;

    const int wm = (wid & 1) * 64;
    const int wn = (wid >> 1) * 32;

    // cp.async mapping: 8 chunks of 16B per thread; tile t, row r, 16B-col c16
    const int pf_t   = tid >> 6;                 // reuse per it: idx = tid+it*256
    (void)pf_t;

    float cacc[4][4][4];
#pragma unroll
    for (int mf = 0; mf < 4; mf++)
#pragma unroll
        for (int nf = 0; nf < 4; nf++)
#pragma unroll
            for (int r = 0; r < 4; r++) cacc[mf][nf][r] = 0.f;

    // ---- prefetch helper (inlined twice) ----
    auto prefetch = [&](int c8, int stage) {
        const uint32_t st = sbase + (uint32_t)stage * (STAGE_W * 4);
        const int k2b = c8 * 16;
#pragma unroll
        for (int it = 0; it < 8; it++) {
            int idx = tid + it * 256;
            int t   = idx >> 9;              // 0..3 tile
            int r   = (idx >> 5) & 15;       // row in tile
            int c16 = idx & 31;              // 16B column
            uint32_t sa = st + (uint32_t)t * TILE_BYTES
                        + ((uint32_t)r * MSTR + (uint32_t)c16 * 4) * 4;
            const uint32_t* g;
            int k2 = k2b + r;
            if (t == 0)      g = g_Ah + (size_t)k2 * NPIX + n0 + c16 * 4;
            else if (t == 1) g = g_Al + (size_t)k2 * NPIX + n0 + c16 * 4;
            else if (t == 2) g = g_Bh + (size_t)k2 * BJP + j0 + c16 * 4;
            else             g = g_Bl + (size_t)k2 * BJP + j0 + c16 * 4;
            CP_ASYNC16(sa, g);
        }
        CP_COMMIT();
    };

    prefetch(0, 0);

    for (int c8 = 0; c8 < 8; c8++) {
        CP_WAIT0();
        __syncthreads();                     // stage (c8&1) full; prior MMA done
        if (c8 < 7) prefetch(c8 + 1, (c8 + 1) & 1);

        const uint32_t* Ahu = (const uint32_t*)sm + (c8 & 1) * STAGE_W;
        const uint32_t* Alu = Ahu + TILEW;
        const uint32_t* Bhu = Alu + TILEW;
        const uint32_t* Blu = Bhu + TILEW;

#pragma unroll
        for (int s = 0; s < 2; s++) {
            const int kb = s * 8;
            uint32_t af[4][4], bh[4][2], bl[4][2];
#pragma unroll
            for (int nf = 0; nf < 4; nf++) {
                int j = wn + nf * 8 + lr;
                bh[nf][0] = Bhu[(kb + lc) * MSTR + j];
                bh[nf][1] = Bhu[(kb + lc + 4) * MSTR + j];
                bl[nf][0] = Blu[(kb + lc) * MSTR + j];
                bl[nf][1] = Blu[(kb + lc + 4) * MSTR + j];
            }
#pragma unroll
            for (int mf = 0; mf < 4; mf++) {
                int p = wm + mf * 16 + lr;
                af[mf][0] = Ahu[(kb + lc) * MSTR + p];
                af[mf][1] = Ahu[(kb + lc) * MSTR + p + 8];
                af[mf][2] = Ahu[(kb + lc + 4) * MSTR + p];
                af[mf][3] = Ahu[(kb + lc + 4) * MSTR + p + 8];
            }
#pragma unroll
            for (int mf = 0; mf < 4; mf++)
#pragma unroll
                for (int nf = 0; nf < 4; nf++) mma16(cacc[mf][nf], af[mf], bh[nf]);
#pragma unroll
            for (int mf = 0; mf < 4; mf++)
#pragma unroll
                for (int nf = 0; nf < 4; nf++) mma16(cacc[mf][nf], af[mf], bl[nf]);
            // reload A-lo into af, do lh
#pragma unroll
            for (int mf = 0; mf < 4; mf++) {
                int p = wm + mf * 16 + lr;
                af[mf][0] = Alu[(kb + lc) * MSTR + p];
                af[mf][1] = Alu[(kb + lc) * MSTR + p + 8];
                af[mf][2] = Alu[(kb + lc + 4) * MSTR + p];
                af[mf][3] = Alu[(kb + lc + 4) * MSTR + p + 8];
            }
#pragma unroll
            for (int mf = 0; mf < 4; mf++)
#pragma unroll
                for (int nf = 0; nf < 4; nf++) mma16(cacc[mf][nf], af[mf], bh[nf]);
        }
    }

    // ---- per-pixel exp partials (from fp32 accumulators, m=0 shift) ----
    float ps[8];
#pragma unroll
    for (int i = 0; i < 8; i++) ps[i] = 0.f;
#pragma unroll
    for (int mf = 0; mf < 4; mf++)
#pragma unroll
        for (int nf = 0; nf < 4; nf++) {
            int j = j0 + wn + nf * 8 + 2 * lc;
            if (j < MEM_DIM) {
                ps[mf * 2 + 0] += __expf(cacc[mf][nf][0]) + __expf(cacc[mf][nf][1]);
                ps[mf * 2 + 1] += __expf(cacc[mf][nf][2]) + __expf(cacc[mf][nf][3]);
            }
        }
#pragma unroll
    for (int i = 0; i < 8; i++) {
        ps[i] += __shfl_xor_sync(0xffffffffu, ps[i], 1);
        ps[i] += __shfl_xor_sync(0xffffffffu, ps[i], 2);
    }
    if (lc == 0) {
        int jw = wid >> 1;
#pragma unroll
        for (int mf = 0; mf < 4; mf++) {
            spart[jw * 128 + wm + mf * 16 + lr]     = ps[mf * 2 + 0];
            spart[jw * 128 + wm + mf * 16 + lr + 8] = ps[mf * 2 + 1];
        }
    }

    // ---- candidate push (z > Z_PUSH covers every possible survivor) ----
#pragma unroll
    for (int mf = 0; mf < 4; mf++) {
#pragma unroll
        for (int nf = 0; nf < 4; nf++) {
            int j = j0 + wn + nf * 8 + 2 * lc;
            if (j >= MEM_DIM) continue;   // j even, MEM_DIM even: j+1 also OK
#pragma unroll
            for (int r = 0; r < 4; r++) {
                float z = cacc[mf][nf][r];
                if (z > Z_PUSH) {
                    int pix = wm + mf * 16 + lr + ((r >> 1) << 3);
                    int jj  = j + (r & 1);
                    int n   = n0 + pix;
                    int grp = n >> 4;
                    int id = atomicAdd(&g_cnt[grp], 1);
                    if (id < CAP2)
                        g_cand[(size_t)grp * CAP2 + id] =
                            make_uint2((uint32_t)(((n & 15) << 16) | jj),
                                       __float_as_uint(z));
                }
            }
        }
    }

    __syncthreads();
    if (tid < 128) {
        float s = spart[tid] + spart[128 + tid] + spart[256 + tid] + spart[384 + tid];
        g_spart[(size_t)blockIdx.y * NPIX + n0 + tid] = s;
    }
}

// ---------------------------------------------------------------------------
// Epilogue: per 16-pixel group (unchanged from R14 — validated).
// ---------------------------------------------------------------------------
#define XSTR 257
#define W_XT   0                       // 16*257 = 4112
#define W_SV   (W_XT + 4112)           // 16
#define W_DNM  (W_SV + 16)             // 16
#define W_TOT  (W_DNM + 16)            // 1
#define W_NS   (W_TOT + 1)             // 1
#define W_OVF  (W_NS + 1)              // 1 (+pad to 8)
#define W_CL   (W_TOT + 8)             // CCAP ints
#define W_SMT  (W_CL + CCAP)           // SCAP ints
#define W_SVL  (W_SMT + SCAP)          // SCAP floats
#define W_YT   (W_SVL + SCAP)          // 4096
#define SMEM_EPI ((W_YT + 4096) * 4)

__global__ void __launch_bounds__(256)
epilogue_kernel(const float* __restrict__ x, const float* __restrict__ Mm,
                float* __restrict__ y, float* __restrict__ att)
{
    extern __shared__ float sm[];
    float* xt   = sm + W_XT;
    float* Sv   = sm + W_SV;
    float* dnm  = sm + W_DNM;
    int*   tot  = (int*)(sm + W_TOT);
    int*   ns   = (int*)(sm + W_NS);
    int*   povf = (int*)(sm + W_OVF);
    int*   clist = (int*)(sm + W_CL);
    int*   smt  = (int*)(sm + W_SMT);
    float* svl  = sm + W_SVL;
    float* yt   = sm + W_YT;

    const int tid = threadIdx.x;
    const int grp = blockIdx.x;
    const int n0  = grp * 16;
    const int b   = n0 >> 10;
    const int hw0 = n0 & 1023;
    float* attb = att + ((size_t)b * MEM_DIM) * HW + hw0;

    if (tid == 0) { *tot = 0; *ns = 0; *povf = 0; }
    if (tid < 16) {
        float s = 0.f;
#pragma unroll
        for (int jb = 0; jb < 16; jb++) s += g_spart[(size_t)jb * NPIX + n0 + tid];
        Sv[tid]  = s;
        dnm[tid] = 0.f;
    }
    // x tile [p][k] for exact recompute
#pragma unroll 4
    for (int idx = tid; idx < FEA * 16; idx += 256) {
        int k = idx >> 4, p2 = idx & 15;
        xt[p2 * XSTR + k] = x[(size_t)b * FEA * HW + (size_t)k * HW + hw0 + p2];
    }
    // att zero-fill (this CTA's [MEM_DIM x 16] slab)
    const float4 z4 = make_float4(0.f, 0.f, 0.f, 0.f);
#pragma unroll 4
    for (int idx = tid; idx < MEM_DIM * 4; idx += 256) {
        int j = idx >> 2, q = (idx & 3) * 4;
        *(float4*)&attb[(size_t)j * HW + q] = z4;
    }
    __syncthreads();

    const int cnt  = g_cnt[grp];
    const uint2* cand = g_cand + (size_t)grp * CAP2;
    const int wwid = tid >> 5, wlane = tid & 31;

    if (cnt <= CAP2) {
        // coarse filter with exact S (pushed z is fp32-split, err ~2e-6)
        for (int e = tid; e < cnt; e += 256) {
            uint2 rec = cand[e];
            int p2 = rec.x >> 16;
            float z = __uint_as_float(rec.y);
            if (__expf(z) > 0.9f * SHRINK * Sv[p2]) {
                int id = atomicAdd(tot, 1);
                if (id < CCAP) clist[id] = (int)rec.x;
                else *povf = 1;
            }
        }
        __syncthreads();
    }

    if (cnt > CAP2 || *povf) {
        // dense exact fallback (statistically unreachable): every (p,j) pair
        for (int t = wwid; t < 16 * MEM_DIM; t += 8) {
            int p2 = t & 15, j = t >> 4;
            const float* mr = Mm + (size_t)j * FEA;
            float a = 0.f;
#pragma unroll
            for (int kk = 0; kk < 8; kk++) {
                int k = kk * 32 + wlane;
                a = fmaf(xt[p2 * XSTR + k], mr[k], a);
            }
#pragma unroll
            for (int d = 16; d > 0; d >>= 1) a += __shfl_xor_sync(0xffffffffu, a, d);
            if (wlane == 0) {
                float we = expf(a) / Sv[p2];
                float d2 = we - SHRINK;
                if (d2 > 0.f) {
                    int id = atomicAdd(ns, 1);
                    if (id < SCAP) {
                        smt[id] = (p2 << 16) | j;
                        svl[id] = d2 * we / (d2 + 1e-12f);
                    }
                }
            }
        }
    } else {
        // warp-exact recompute of shortlist, precise decide
        const int T = min(*tot, CCAP);
        for (int e = wwid; e < T; e += 8) {
            int meta = clist[e];
            int p2 = meta >> 16, j = meta & 0xffff;
            const float* mr = Mm + (size_t)j * FEA;
            float a = 0.f;
#pragma unroll
            for (int kk = 0; kk < 8; kk++) {
                int k = kk * 32 + wlane;
                a = fmaf(xt[p2 * XSTR + k], mr[k], a);
            }
#pragma unroll
            for (int d = 16; d > 0; d >>= 1) a += __shfl_xor_sync(0xffffffffu, a, d);
            if (wlane == 0) {
                float we = expf(a) / Sv[p2];
                float d2 = we - SHRINK;
                if (d2 > 0.f) {
                    int id = atomicAdd(ns, 1);
                    if (id < SCAP) {
                        smt[id] = meta;
                        svl[id] = d2 * we / (d2 + 1e-12f);
                    }
                }
            }
        }
    }
    __syncthreads();

    const int NS = min(*ns, SCAP);
    // denom per pixel
    for (int e = tid; e < NS; e += 256) atomicAdd(&dnm[smt[e] >> 16], svl[e]);
    __syncthreads();
    if (tid < 16) dnm[tid] = 1.f / fmaxf(dnm[tid], 1e-12f);
    __syncthreads();

    // sparse att scatter (slab already zeroed by this CTA)
    for (int e = tid; e < NS; e += 256) {
        int p2 = smt[e] >> 16, j = smt[e] & 0xffff;
        attb[(size_t)j * HW + p2] = svl[e] * dnm[p2];
    }

    // sparse y -> yt (warp per pixel)
    for (int pp = wwid; pp < 16; pp += 8) {
        float acc[8] = {0, 0, 0, 0, 0, 0, 0, 0};
        float idn = dnm[pp];
        for (int e = 0; e < NS; e++) {
            if ((smt[e] >> 16) != pp) continue;
            float aval = svl[e] * idn;
            const float* mr = Mm + (size_t)(smt[e] & 0xffff) * FEA;
#pragma unroll
            for (int r = 0; r < 8; r++)
                acc[r] = fmaf(aval, mr[r * 32 + wlane], acc[r]);
        }
#pragma unroll
        for (int r = 0; r < 8; r++) yt[pp * 256 + r * 32 + wlane] = acc[r];
    }
    __syncthreads();

    // y[b][c][h][w], 64B per c-row
    float* yb = y + ((size_t)b * FEA) * HW + hw0;
#pragma unroll 4
    for (int idx = tid; idx < 16 * FEA; idx += 256) {
        int c = idx >> 4, pp = idx & 15;
        yb[(size_t)c * HW + pp] = yt[pp * 256 + c];
    }
}

// ---------------------------------------------------------------------------
extern "C" void kernel_launch(void* const* d_in, const int* in_sizes, int n_in,
                              void* d_out, int out_size)
{
    const float* x  = (const float*)d_in[0];
    const float* Mm = (const float*)d_in[1];
    if (in_sizes[0] == MEM_DIM * FEA && in_sizes[1] == NPIX * FEA) {
        const float* t = x; x = Mm; Mm = t;
    }

    float* y   = (float*)d_out;
    float* att = (float*)d_out + (size_t)32 * FEA * HW;

    zero_cnt_kernel<<<NGRP / 256, 256>>>();

    dim3 ga(NPIX / 256, 128);
    split_a_kernel<<<ga, 256>>>(x);
    split_b_kernel<<<(MEM_DIM * 128 + 255) / 256, 256>>>(Mm);

    cudaFuncSetAttribute(gemm1_tc,
                         cudaFuncAttributeMaxDynamicSharedMemorySize, GEMM_SMEM);
    dim3 g1(NPIX / 128, 16);
    gemm1_tc<<<g1, 256, GEMM_SMEM>>>(x, Mm);

    cudaFuncSetAttribute(epilogue_kernel,
                         cudaFuncAttributeMaxDynamicSharedMemorySize, SMEM_EPI);
    epilogue_kernel<<<NGRP, 256, SMEM_EPI>>>(x, Mm, y, att);
}